// round 2
// baseline (speedup 1.0000x reference)
#include <cuda_runtime.h>
#include <cstdint>
#include <cstddef>

#define HW   4096
#define NB   32
#define CIN  256
#define CMC  64
#define MTOT 384
#define KCAT 192

// ---------------- scratch (static device globals; no allocation) ----------------
__device__ float d_mean[NB * CIN];                       // 32 KB
__device__ float d_ker[NB * CMC * 43];                   // 344 KB
__device__ float d_Wcat[MTOT * KCAT];                    // 288 KB
__device__ float d_cbias[MTOT];
__device__ float d_f[(size_t)NB * CMC * HW];             // 33.5 MB
__device__ float d_ocat[(size_t)NB * KCAT * HW];         // 100.7 MB

// ---------------- f32x2 helpers ----------------
__device__ __forceinline__ unsigned long long pack2(float a) {
    unsigned long long r;
    asm("mov.b64 %0, {%1, %1};" : "=l"(r) : "f"(a));
    return r;
}
__device__ __forceinline__ void fma2(unsigned long long& d, unsigned long long a,
                                     unsigned long long b) {
    asm("fma.rn.f32x2 %0, %1, %2, %0;" : "+l"(d) : "l"(a), "l"(b));
}
__device__ __forceinline__ float2 unpack2(unsigned long long v) {
    float2 f;
    asm("mov.b64 {%0, %1}, %2;" : "=f"(f.x), "=f"(f.y) : "l"(v));
    return f;
}

// ---------------- K1: per-(n,c) spatial mean ----------------
__global__ void __launch_bounds__(256) mean_kernel(const float* __restrict__ x) {
    const int idx = blockIdx.x;  // n*256 + c
    const float4* p = reinterpret_cast<const float4*>(x + (size_t)idx * HW);
    float s = 0.f;
#pragma unroll
    for (int i = 0; i < 4; i++) {
        float4 v = p[threadIdx.x + i * 256];
        s += (v.x + v.y) + (v.z + v.w);
    }
#pragma unroll
    for (int o = 16; o; o >>= 1) s += __shfl_down_sync(0xffffffffu, s, o);
    __shared__ float ws[8];
    if ((threadIdx.x & 31) == 0) ws[threadIdx.x >> 5] = s;
    __syncthreads();
    if (threadIdx.x < 8) {
        float t = ws[threadIdx.x];
#pragma unroll
        for (int o = 4; o; o >>= 1) t += __shfl_down_sync(0xffu, t, o);
        if (threadIdx.x == 0) d_mean[idx] = t * (1.f / 4096.f);
    }
}

// ---------------- K2a: g = relu(conv_w@mean + b); build dynamic kernels ----------------
__global__ void __launch_bounds__(256) gker_kernel(
    const float* __restrict__ conv_w, const float* __restrict__ conv_b,
    const float* __restrict__ ckw, const float* __restrict__ ckb,
    const float* __restrict__ ck2w, const float* __restrict__ ck2b,
    const float* __restrict__ ckd4w, const float* __restrict__ ckd4b,
    const float* __restrict__ kw, const float* __restrict__ kb,
    const float* __restrict__ k2w, const float* __restrict__ k2b,
    const float* __restrict__ kd4w, const float* __restrict__ kd4b) {
    const int t = blockIdx.x * 256 + threadIdx.x;  // 0..2047 => (n, c)
    const int n = t >> 6, c = t & 63;
    const float* mrow = &d_mean[n * CIN];
    const float* wrow = &conv_w[c * CIN];
    float s = conv_b[c];
#pragma unroll 8
    for (int k = 0; k < CIN; k++) s = fmaf(mrow[k], wrow[k], s);
    const float g = fmaxf(s, 0.f);
    float* kp = &d_ker[(size_t)t * 43];
    float a = *ckw, b = *ckb;
#pragma unroll
    for (int i = 0; i < 25; i++) kp[i] = fmaf(a, fmaf(g, kw[i], kb[i]), b);
    a = *ck2w; b = *ck2b;
#pragma unroll
    for (int i = 0; i < 9; i++) kp[25 + i] = fmaf(a, fmaf(g, k2w[i], k2b[i]), b);
    a = *ckd4w; b = *ckd4b;
#pragma unroll
    for (int i = 0; i < 9; i++) kp[34 + i] = fmaf(a, fmaf(g, kd4w[i], kd4b[i]), b);
}

// ---------------- K2b: collapsed weights Wcat[o][b*64+c] and cbias ----------------
__global__ void __launch_bounds__(256) wcat_kernel(
    const float* __restrict__ fc_w, const float* __restrict__ fc_b,
    const float* __restrict__ fuse_w, const float* __restrict__ fuse_b) {
    const int m = blockIdx.x * 256 + threadIdx.x;
    if (m < MTOT * KCAT) {
        const int o = m / KCAT, cs = m % KCAT;
        const int b = cs >> 6, c = cs & 63;
        const float* fcr = &fc_w[o * 384 + b * 128];
        float s = 0.f;
#pragma unroll 4
        for (int j = 0; j < 128; j++) s = fmaf(fcr[j], fuse_w[j * 64 + c], s);
        d_Wcat[m] = s;
    } else {
        const int o = m - MTOT * KCAT;
        if (o < MTOT) {
            float s = fc_b[o];
            for (int j = 0; j < 384; j++)
                s = fmaf(fc_w[o * 384 + j], fuse_b[j & 127], s);
            d_cbias[o] = s;
        }
    }
}

// ---------------- shared GEMM: C[n][o][p] = act(A[o][:]@B[n][:][p] + bias[o]) ----------------
// block tile: 64 o x 128 p; threads 256 as (tx=pixel-group 16, ty=o-group 16);
// thread tile: 4 o x 4 pixel-pairs (f32x2).
template <int KDIM, bool RELU>
__global__ void __launch_bounds__(256) gemm_kernel(
    const float* __restrict__ A, const float* __restrict__ B,
    const float* __restrict__ bias, float* __restrict__ C, int Mtotal) {
    const int o0 = blockIdx.x * 64;
    const int p0 = blockIdx.y * 128;
    const int n = blockIdx.z;
    const float* Bn = B + (size_t)n * KDIM * HW;
    float* Cn = C + (size_t)n * Mtotal * HW;

    __shared__ __align__(16) float As[16][68];
    __shared__ __align__(16) float Bs[16][128];

    const int tid = threadIdx.x;
    const int tx = tid & 15;   // pixel group: pixels p0 + 2*tx + 32*pp
    const int ty = tid >> 4;   // o group: o0 + ty*4 + i

    unsigned long long acc[4][4];
#pragma unroll
    for (int i = 0; i < 4; i++)
#pragma unroll
        for (int j = 0; j < 4; j++) acc[i][j] = 0ull;

    for (int k0 = 0; k0 < KDIM; k0 += 16) {
        // A tile: 64 rows x 16 k (transposed store As[k][o])
        {
            const int r = tid >> 2;
            const int kq = (tid & 3) << 2;
            const float4 av = *reinterpret_cast<const float4*>(
                &A[(size_t)(o0 + r) * KDIM + k0 + kq]);
            As[kq + 0][r] = av.x;
            As[kq + 1][r] = av.y;
            As[kq + 2][r] = av.z;
            As[kq + 3][r] = av.w;
        }
        // B tile: 16 rows x 128 p
#pragma unroll
        for (int i = 0; i < 2; i++) {
            const int idx = tid + i * 256;
            const int r = idx >> 5;
            const int c4 = (idx & 31) << 2;
            *reinterpret_cast<float4*>(&Bs[r][c4]) =
                *reinterpret_cast<const float4*>(
                    &Bn[(size_t)(k0 + r) * HW + p0 + c4]);
        }
        __syncthreads();
#pragma unroll
        for (int k = 0; k < 16; k++) {
            unsigned long long av[4], bv[4];
#pragma unroll
            for (int i = 0; i < 4; i++) av[i] = pack2(As[k][ty * 4 + i]);
#pragma unroll
            for (int pp = 0; pp < 4; pp++)
                bv[pp] = *reinterpret_cast<const unsigned long long*>(
                    &Bs[k][2 * tx + 32 * pp]);
#pragma unroll
            for (int i = 0; i < 4; i++)
#pragma unroll
                for (int pp = 0; pp < 4; pp++) fma2(acc[i][pp], av[i], bv[pp]);
        }
        __syncthreads();
    }
#pragma unroll
    for (int i = 0; i < 4; i++) {
        const int o = o0 + ty * 4 + i;
        const float bv = bias[o];
#pragma unroll
        for (int pp = 0; pp < 4; pp++) {
            float2 v = unpack2(acc[i][pp]);
            v.x += bv;
            v.y += bv;
            if (RELU) {
                v.x = fmaxf(v.x, 0.f);
                v.y = fmaxf(v.y, 0.f);
            }
            *reinterpret_cast<float2*>(&Cn[(size_t)o * HW + p0 + 2 * tx + 32 * pp]) = v;
        }
    }
}

// ---------------- K4a: three depthwise convs, smem 72x72 zero-padded tile ----------------
__global__ void __launch_bounds__(256) dw_kernel() {
    const int c = blockIdx.x;  // 64
    const int n = blockIdx.y;  // 32
    __shared__ float sm[72 * 72];
    __shared__ float kk[43];
    const int tid = threadIdx.x;
    for (int i = tid; i < 72 * 72; i += 256) sm[i] = 0.f;
    __syncthreads();
    const float* fb = d_f + ((size_t)n * CMC + c) * HW;
    for (int i = tid; i < HW; i += 256)
        sm[((i >> 6) + 4) * 72 + (i & 63) + 4] = fb[i];
    if (tid < 43) kk[tid] = d_ker[((size_t)n * CMC + c) * 43 + tid];
    __syncthreads();

    float* o1 = d_ocat + ((size_t)n * KCAT + c) * HW;
    float* o2 = o1 + (size_t)64 * HW;
    float* o3 = o1 + (size_t)128 * HW;

    for (int i = tid; i < HW; i += 256) {
        const int h = i >> 6, w = i & 63;
        float s1 = 0.f, s2 = 0.f, s3 = 0.f;
#pragma unroll
        for (int dy = 0; dy < 5; dy++)
#pragma unroll
            for (int dx = 0; dx < 5; dx++)
                s1 = fmaf(kk[dy * 5 + dx], sm[(h + dy + 2) * 72 + w + dx + 2], s1);
#pragma unroll
        for (int dy = 0; dy < 3; dy++)
#pragma unroll
            for (int dx = 0; dx < 3; dx++) {
                s2 = fmaf(kk[25 + dy * 3 + dx], sm[(h + 2 * dy + 2) * 72 + w + 2 * dx + 2], s2);
                s3 = fmaf(kk[34 + dy * 3 + dx], sm[(h + 4 * dy) * 72 + w + 4 * dx], s3);
            }
        o1[i] = s1;
        o2[i] = s2;
        o3[i] = s3;
    }
}

// ---------------- host launch ----------------
extern "C" void kernel_launch(void* const* d_in, const int* in_sizes, int n_in,
                              void* d_out, int out_size) {
    (void)in_sizes; (void)n_in; (void)out_size;
    const float* x      = (const float*)d_in[0];
    const float* conv_w = (const float*)d_in[1];
    const float* conv_b = (const float*)d_in[2];
    const float* ckw    = (const float*)d_in[3];
    const float* ckb    = (const float*)d_in[4];
    const float* ck2w   = (const float*)d_in[5];
    const float* ck2b   = (const float*)d_in[6];
    const float* ckd4w  = (const float*)d_in[7];
    const float* ckd4b  = (const float*)d_in[8];
    const float* kw     = (const float*)d_in[9];
    const float* kb     = (const float*)d_in[10];
    const float* k2w    = (const float*)d_in[11];
    const float* k2b    = (const float*)d_in[12];
    const float* kd4w   = (const float*)d_in[13];
    const float* kd4b   = (const float*)d_in[14];
    const float* fuse_w = (const float*)d_in[15];
    const float* fuse_b = (const float*)d_in[16];
    const float* fc_w   = (const float*)d_in[17];
    const float* fc_b   = (const float*)d_in[18];
    float* out = (float*)d_out;

    void *p_f = nullptr, *p_ocat = nullptr, *p_Wcat = nullptr, *p_cbias = nullptr;
    cudaGetSymbolAddress(&p_f, d_f);
    cudaGetSymbolAddress(&p_ocat, d_ocat);
    cudaGetSymbolAddress(&p_Wcat, d_Wcat);
    cudaGetSymbolAddress(&p_cbias, d_cbias);

    // K1: spatial means
    mean_kernel<<<NB * CIN, 256>>>(x);
    // K2a: g + dynamic depthwise kernels
    gker_kernel<<<8, 256>>>(conv_w, conv_b, ckw, ckb, ck2w, ck2b, ckd4w, ckd4b,
                            kw, kb, k2w, k2b, kd4w, kd4b);
    // K2b: collapsed fuse+fc weights (independent of x)
    wcat_kernel<<<(MTOT * KCAT + MTOT + 255) / 256, 256>>>(fc_w, fc_b, fuse_w, fuse_b);
    // K3: f = relu(1x1 conv 256->64)
    gemm_kernel<CIN, true><<<dim3(1, HW / 128, NB), 256>>>(
        conv_w, x, conv_b, (float*)p_f, CMC);
    // K4a: dynamic depthwise (3 branches) -> ocat[n][192][p]
    dw_kernel<<<dim3(CMC, NB), 256>>>();
    // K4b: out = Wcat @ ocat + cbias
    gemm_kernel<KCAT, false><<<dim3(MTOT / 64, HW / 128, NB), 256>>>(
        (const float*)p_Wcat, (const float*)p_ocat, (const float*)p_cbias, out, MTOT);
}

// round 5
// speedup vs baseline: 1.4041x; 1.4041x over previous
#include <cuda_runtime.h>
#include <cstdint>
#include <cstddef>

#define HW   4096
#define NB   32
#define CIN  256
#define CMC  64
#define MTOT 384
#define KCAT 192

// ---------------- scratch (static device globals; no allocation) ----------------
__device__ float d_mean[NB * CIN];                       // 32 KB
__device__ float d_ker[NB * CMC * 43];                   // 344 KB
__device__ float d_Wcat[MTOT * KCAT];                    // 288 KB (tf32-rounded)
__device__ float d_cbias[MTOT];
__device__ float d_f[(size_t)NB * CMC * HW];             // 33.5 MB
__device__ float d_ocat[(size_t)NB * KCAT * HW];         // 100.7 MB (tf32-rounded)

// ---------------- helpers ----------------
__device__ __forceinline__ unsigned long long pack2(float a) {
    unsigned long long r;
    asm("mov.b64 %0, {%1, %1};" : "=l"(r) : "f"(a));
    return r;
}
__device__ __forceinline__ void fma2(unsigned long long& d, unsigned long long a,
                                     unsigned long long b) {
    asm("fma.rn.f32x2 %0, %1, %2, %0;" : "+l"(d) : "l"(a), "l"(b));
}
__device__ __forceinline__ float2 unpack2(unsigned long long v) {
    float2 f;
    asm("mov.b64 {%0, %1}, %2;" : "=f"(f.x), "=f"(f.y) : "l"(v));
    return f;
}
// round-to-nearest tf32 (bit pattern kept in a float)
__device__ __forceinline__ float f2tf32(float f) {
    uint32_t r;
    asm("cvt.rna.tf32.f32 %0, %1;" : "=r"(r) : "f"(f));
    return __uint_as_float(r);
}
__device__ __forceinline__ void mma_tf32(float c[4], const uint32_t a[4],
                                         const uint32_t b[2]) {
    asm volatile(
        "mma.sync.aligned.m16n8k8.row.col.f32.tf32.tf32.f32 "
        "{%0,%1,%2,%3}, {%4,%5,%6,%7}, {%8,%9}, {%0,%1,%2,%3};"
        : "+f"(c[0]), "+f"(c[1]), "+f"(c[2]), "+f"(c[3])
        : "r"(a[0]), "r"(a[1]), "r"(a[2]), "r"(a[3]), "r"(b[0]), "r"(b[1]));
}

// ---------------- K1: per-(n,c) spatial mean ----------------
__global__ void __launch_bounds__(256) mean_kernel(const float* __restrict__ x) {
    const int idx = blockIdx.x;  // n*256 + c
    const float4* p = reinterpret_cast<const float4*>(x + (size_t)idx * HW);
    float s = 0.f;
#pragma unroll
    for (int i = 0; i < 4; i++) {
        float4 v = p[threadIdx.x + i * 256];
        s += (v.x + v.y) + (v.z + v.w);
    }
#pragma unroll
    for (int o = 16; o; o >>= 1) s += __shfl_down_sync(0xffffffffu, s, o);
    __shared__ float ws[8];
    if ((threadIdx.x & 31) == 0) ws[threadIdx.x >> 5] = s;
    __syncthreads();
    if (threadIdx.x < 8) {
        float t = ws[threadIdx.x];
#pragma unroll
        for (int o = 4; o; o >>= 1) t += __shfl_down_sync(0xffu, t, o);
        if (threadIdx.x == 0) d_mean[idx] = t * (1.f / 4096.f);
    }
}

// ---------------- K2a: g = relu(conv_w@mean + b); build dynamic kernels ----------------
__global__ void __launch_bounds__(256) gker_kernel(
    const float* __restrict__ conv_w, const float* __restrict__ conv_b,
    const float* __restrict__ ckw, const float* __restrict__ ckb,
    const float* __restrict__ ck2w, const float* __restrict__ ck2b,
    const float* __restrict__ ckd4w, const float* __restrict__ ckd4b,
    const float* __restrict__ kw, const float* __restrict__ kb,
    const float* __restrict__ k2w, const float* __restrict__ k2b,
    const float* __restrict__ kd4w, const float* __restrict__ kd4b) {
    const int t = blockIdx.x * 256 + threadIdx.x;  // 0..2047 => (n, c)
    const int n = t >> 6, c = t & 63;
    const float* mrow = &d_mean[n * CIN];
    const float* wrow = &conv_w[c * CIN];
    float s = conv_b[c];
#pragma unroll 8
    for (int k = 0; k < CIN; k++) s = fmaf(mrow[k], wrow[k], s);
    const float g = fmaxf(s, 0.f);
    float* kp = &d_ker[(size_t)t * 43];
    float a = *ckw, b = *ckb;
#pragma unroll
    for (int i = 0; i < 25; i++) kp[i] = fmaf(a, fmaf(g, kw[i], kb[i]), b);
    a = *ck2w; b = *ck2b;
#pragma unroll
    for (int i = 0; i < 9; i++) kp[25 + i] = fmaf(a, fmaf(g, k2w[i], k2b[i]), b);
    a = *ckd4w; b = *ckd4b;
#pragma unroll
    for (int i = 0; i < 9; i++) kp[34 + i] = fmaf(a, fmaf(g, kd4w[i], kd4b[i]), b);
}

// ---------------- K2b: collapsed weights Wcat (tf32-rounded) and cbias ----------------
__global__ void __launch_bounds__(256) wcat_kernel(
    const float* __restrict__ fc_w, const float* __restrict__ fc_b,
    const float* __restrict__ fuse_w, const float* __restrict__ fuse_b) {
    const int m = blockIdx.x * 256 + threadIdx.x;
    if (m < MTOT * KCAT) {
        const int o = m / KCAT, cs = m % KCAT;
        const int b = cs >> 6, c = cs & 63;
        const float* fcr = &fc_w[o * 384 + b * 128];
        float s = 0.f;
#pragma unroll 4
        for (int j = 0; j < 128; j++) s = fmaf(fcr[j], fuse_w[j * 64 + c], s);
        d_Wcat[m] = f2tf32(s);
    } else {
        const int o = m - MTOT * KCAT;
        if (o < MTOT) {
            float s = fc_b[o];
            for (int j = 0; j < 384; j++)
                s = fmaf(fc_w[o * 384 + j], fuse_b[j & 127], s);
            d_cbias[o] = s;
        }
    }
}

// ---------------- K3 GEMM (fp32 FFMA2): C = act(A@B + bias) ----------------
template <int KDIM, bool RELU>
__global__ void __launch_bounds__(256) gemm_kernel(
    const float* __restrict__ A, const float* __restrict__ B,
    const float* __restrict__ bias, float* __restrict__ C, int Mtotal) {
    const int o0 = blockIdx.x * 64;
    const int p0 = blockIdx.y * 128;
    const int n = blockIdx.z;
    const float* Bn = B + (size_t)n * KDIM * HW;
    float* Cn = C + (size_t)n * Mtotal * HW;

    __shared__ __align__(16) float As[16][68];
    __shared__ __align__(16) float Bs[16][128];

    const int tid = threadIdx.x;
    const int tx = tid & 15;
    const int ty = tid >> 4;

    unsigned long long acc[4][4];
#pragma unroll
    for (int i = 0; i < 4; i++)
#pragma unroll
        for (int j = 0; j < 4; j++) acc[i][j] = 0ull;

    for (int k0 = 0; k0 < KDIM; k0 += 16) {
        {
            const int r = tid >> 2;
            const int kq = (tid & 3) << 2;
            const float4 av = *reinterpret_cast<const float4*>(
                &A[(size_t)(o0 + r) * KDIM + k0 + kq]);
            As[kq + 0][r] = av.x;
            As[kq + 1][r] = av.y;
            As[kq + 2][r] = av.z;
            As[kq + 3][r] = av.w;
        }
#pragma unroll
        for (int i = 0; i < 2; i++) {
            const int idx = tid + i * 256;
            const int r = idx >> 5;
            const int c4 = (idx & 31) << 2;
            *reinterpret_cast<float4*>(&Bs[r][c4]) =
                *reinterpret_cast<const float4*>(
                    &Bn[(size_t)(k0 + r) * HW + p0 + c4]);
        }
        __syncthreads();
#pragma unroll
        for (int k = 0; k < 16; k++) {
            unsigned long long av[4], bv[4];
#pragma unroll
            for (int i = 0; i < 4; i++) av[i] = pack2(As[k][ty * 4 + i]);
#pragma unroll
            for (int pp = 0; pp < 4; pp++)
                bv[pp] = *reinterpret_cast<const unsigned long long*>(
                    &Bs[k][2 * tx + 32 * pp]);
#pragma unroll
            for (int i = 0; i < 4; i++)
#pragma unroll
                for (int pp = 0; pp < 4; pp++) fma2(acc[i][pp], av[i], bv[pp]);
        }
        __syncthreads();
    }
#pragma unroll
    for (int i = 0; i < 4; i++) {
        const int o = o0 + ty * 4 + i;
        const float bv = bias[o];
#pragma unroll
        for (int pp = 0; pp < 4; pp++) {
            float2 v = unpack2(acc[i][pp]);
            v.x += bv;
            v.y += bv;
            if (RELU) {
                v.x = fmaxf(v.x, 0.f);
                v.y = fmaxf(v.y, 0.f);
            }
            *reinterpret_cast<float2*>(&Cn[(size_t)o * HW + p0 + 2 * tx + 32 * pp]) = v;
        }
    }
}

// ---------------- K4b: tf32 tensor-core GEMM: out = Wcat @ ocat + cbias ----------------
// block 128o x 128px, 8 warps (2 m x 4 n), warp tile 64o x 32px, k-tile 16.
// Operands are pre-rounded to tf32 by their producers.
__global__ void __launch_bounds__(256) gemm_mma_kernel(
    const float* __restrict__ A, const float* __restrict__ B,
    const float* __restrict__ bias, float* __restrict__ C) {
    const int o0 = blockIdx.x * 128;
    const int p0 = blockIdx.y * 128;
    const int n = blockIdx.z;
    const float* Bn = B + (size_t)n * KCAT * HW;
    float* Cn = C + (size_t)n * MTOT * HW;

    __shared__ __align__(16) float As[128][20];   // [m][k], stride 20 (conflict-free)
    __shared__ __align__(16) float Bs[16][136];   // [k][p], stride 136 (conflict-free)

    const int tid = threadIdx.x;
    const int wid = tid >> 5, lane = tid & 31;
    const int wm = wid >> 2, wn = wid & 3;      // warp grid 2 x 4
    const int g = lane >> 2, tg = lane & 3;     // mma fragment coords

    float acc[4][4][4];
#pragma unroll
    for (int i = 0; i < 4; i++)
#pragma unroll
        for (int j = 0; j < 4; j++)
#pragma unroll
            for (int q = 0; q < 4; q++) acc[i][j][q] = 0.f;

    for (int k0 = 0; k0 < KCAT; k0 += 16) {
        // stage A tile: 128 m x 16 k
        {
            const int m = tid >> 1;
            const int ko = (tid & 1) * 8;
            const float* src = &A[(size_t)(o0 + m) * KCAT + k0 + ko];
            float4 v0 = *reinterpret_cast<const float4*>(src);
            float4 v1 = *reinterpret_cast<const float4*>(src + 4);
            *reinterpret_cast<float4*>(&As[m][ko]) = v0;
            *reinterpret_cast<float4*>(&As[m][ko + 4]) = v1;
        }
        // stage B tile: 16 k x 128 px
        {
            const int kb = tid >> 4;
            const int pb = (tid & 15) * 8;
            const float* src = &Bn[(size_t)(k0 + kb) * HW + p0 + pb];
            float4 u0 = *reinterpret_cast<const float4*>(src);
            float4 u1 = *reinterpret_cast<const float4*>(src + 4);
            *reinterpret_cast<float4*>(&Bs[kb][pb]) = u0;
            *reinterpret_cast<float4*>(&Bs[kb][pb + 4]) = u1;
        }
        __syncthreads();
#pragma unroll
        for (int ks = 0; ks < 16; ks += 8) {
            uint32_t af[4][4], bf[4][2];
#pragma unroll
            for (int i = 0; i < 4; i++) {
                const int m = wm * 64 + i * 16 + g;
                af[i][0] = __float_as_uint(As[m][ks + tg]);
                af[i][1] = __float_as_uint(As[m + 8][ks + tg]);
                af[i][2] = __float_as_uint(As[m][ks + tg + 4]);
                af[i][3] = __float_as_uint(As[m + 8][ks + tg + 4]);
            }
#pragma unroll
            for (int j = 0; j < 4; j++) {
                const int col = wn * 32 + j * 8 + g;
                bf[j][0] = __float_as_uint(Bs[ks + tg][col]);
                bf[j][1] = __float_as_uint(Bs[ks + tg + 4][col]);
            }
#pragma unroll
            for (int i = 0; i < 4; i++)
#pragma unroll
                for (int j = 0; j < 4; j++) mma_tf32(acc[i][j], af[i], bf[j]);
        }
        __syncthreads();
    }
    // epilogue
#pragma unroll
    for (int i = 0; i < 4; i++) {
        const int o = o0 + wm * 64 + i * 16 + g;
        const float bv0 = bias[o];
        const float bv1 = bias[o + 8];
#pragma unroll
        for (int j = 0; j < 4; j++) {
            const int px = p0 + wn * 32 + j * 8 + 2 * tg;
            float2 v0 = make_float2(acc[i][j][0] + bv0, acc[i][j][1] + bv0);
            float2 v1 = make_float2(acc[i][j][2] + bv1, acc[i][j][3] + bv1);
            *reinterpret_cast<float2*>(&Cn[(size_t)o * HW + px]) = v0;
            *reinterpret_cast<float2*>(&Cn[(size_t)(o + 8) * HW + px]) = v1;
        }
    }
}

// ---------------- K4a: three depthwise convs, smem 72x72 zero-padded tile ----------------
__global__ void __launch_bounds__(256) dw_kernel() {
    const int c = blockIdx.x;  // 64
    const int n = blockIdx.y;  // 32
    __shared__ float sm[72 * 72];
    __shared__ float kk[43];
    const int tid = threadIdx.x;
    for (int i = tid; i < 72 * 72; i += 256) sm[i] = 0.f;
    __syncthreads();
    const float* fb = d_f + ((size_t)n * CMC + c) * HW;
    for (int i = tid; i < HW; i += 256)
        sm[((i >> 6) + 4) * 72 + (i & 63) + 4] = fb[i];
    if (tid < 43) kk[tid] = d_ker[((size_t)n * CMC + c) * 43 + tid];
    __syncthreads();

    float* o1 = d_ocat + ((size_t)n * KCAT + c) * HW;
    float* o2 = o1 + (size_t)64 * HW;
    float* o3 = o1 + (size_t)128 * HW;

    for (int i = tid; i < HW; i += 256) {
        const int h = i >> 6, w = i & 63;
        float s1 = 0.f, s2 = 0.f, s3 = 0.f;
#pragma unroll
        for (int dy = 0; dy < 5; dy++)
#pragma unroll
            for (int dx = 0; dx < 5; dx++)
                s1 = fmaf(kk[dy * 5 + dx], sm[(h + dy + 2) * 72 + w + dx + 2], s1);
#pragma unroll
        for (int dy = 0; dy < 3; dy++)
#pragma unroll
            for (int dx = 0; dx < 3; dx++) {
                s2 = fmaf(kk[25 + dy * 3 + dx], sm[(h + 2 * dy + 2) * 72 + w + 2 * dx + 2], s2);
                s3 = fmaf(kk[34 + dy * 3 + dx], sm[(h + 4 * dy) * 72 + w + 4 * dx], s3);
            }
        // pre-round to tf32 so the mma GEMM needs no conversion
        o1[i] = f2tf32(s1);
        o2[i] = f2tf32(s2);
        o3[i] = f2tf32(s3);
    }
}

// ---------------- host launch ----------------
extern "C" void kernel_launch(void* const* d_in, const int* in_sizes, int n_in,
                              void* d_out, int out_size) {
    (void)in_sizes; (void)n_in; (void)out_size;
    const float* x      = (const float*)d_in[0];
    const float* conv_w = (const float*)d_in[1];
    const float* conv_b = (const float*)d_in[2];
    const float* ckw    = (const float*)d_in[3];
    const float* ckb    = (const float*)d_in[4];
    const float* ck2w   = (const float*)d_in[5];
    const float* ck2b   = (const float*)d_in[6];
    const float* ckd4w  = (const float*)d_in[7];
    const float* ckd4b  = (const float*)d_in[8];
    const float* kw     = (const float*)d_in[9];
    const float* kb     = (const float*)d_in[10];
    const float* k2w    = (const float*)d_in[11];
    const float* k2b    = (const float*)d_in[12];
    const float* kd4w   = (const float*)d_in[13];
    const float* kd4b   = (const float*)d_in[14];
    const float* fuse_w = (const float*)d_in[15];
    const float* fuse_b = (const float*)d_in[16];
    const float* fc_w   = (const float*)d_in[17];
    const float* fc_b   = (const float*)d_in[18];
    float* out = (float*)d_out;

    void *p_f = nullptr, *p_ocat = nullptr, *p_Wcat = nullptr, *p_cbias = nullptr;
    cudaGetSymbolAddress(&p_f, d_f);
    cudaGetSymbolAddress(&p_ocat, d_ocat);
    cudaGetSymbolAddress(&p_Wcat, d_Wcat);
    cudaGetSymbolAddress(&p_cbias, d_cbias);

    // K1: spatial means
    mean_kernel<<<NB * CIN, 256>>>(x);
    // K2a: g + dynamic depthwise kernels
    gker_kernel<<<8, 256>>>(conv_w, conv_b, ckw, ckb, ck2w, ck2b, ckd4w, ckd4b,
                            kw, kb, k2w, k2b, kd4w, kd4b);
    // K2b: collapsed fuse+fc weights (tf32-rounded)
    wcat_kernel<<<(MTOT * KCAT + MTOT + 255) / 256, 256>>>(fc_w, fc_b, fuse_w, fuse_b);
    // K3: f = relu(1x1 conv 256->64), fp32
    gemm_kernel<CIN, true><<<dim3(1, HW / 128, NB), 256>>>(
        conv_w, x, conv_b, (float*)p_f, CMC);
    // K4a: dynamic depthwise (3 branches) -> ocat[n][192][p], tf32-rounded
    dw_kernel<<<dim3(CMC, NB), 256>>>();
    // K4b: out = Wcat @ ocat + cbias  (tf32 tensor cores)
    gemm_mma_kernel<<<dim3(MTOT / 128, HW / 128, NB), 256>>>(
        (const float*)p_Wcat, (const float*)p_ocat, (const float*)p_cbias, out);
}

// round 7
// speedup vs baseline: 1.5400x; 1.0968x over previous
#include <cuda_runtime.h>
#include <cstdint>
#include <cstddef>

#define HW   4096
#define NB   32
#define CIN  256
#define CMC  64
#define MTOT 384
#define KCAT 192

// ---------------- scratch (static device globals; no allocation) ----------------
__device__ float d_mean[NB * CIN];                       // 32 KB
__device__ float d_ker[NB * CMC * 43];                   // 344 KB
__device__ float d_Wcat[MTOT * KCAT];                    // 288 KB (tf32-rounded)
__device__ float d_cbias[MTOT];
__device__ float d_f[(size_t)NB * CMC * HW];             // 33.5 MB
__device__ float d_ocat[(size_t)NB * KCAT * HW];         // 100.7 MB (tf32-rounded)

// ---------------- helpers ----------------
__device__ __forceinline__ float f2tf32(float f) {
    uint32_t r;
    asm("cvt.rna.tf32.f32 %0, %1;" : "=r"(r) : "f"(f));
    return __uint_as_float(r);
}
__device__ __forceinline__ float4 cvt4(float4 v) {
    v.x = f2tf32(v.x); v.y = f2tf32(v.y); v.z = f2tf32(v.z); v.w = f2tf32(v.w);
    return v;
}
__device__ __forceinline__ void mma_tf32(float c[4], const uint32_t a[4],
                                         const uint32_t b[2]) {
    asm volatile(
        "mma.sync.aligned.m16n8k8.row.col.f32.tf32.tf32.f32 "
        "{%0,%1,%2,%3}, {%4,%5,%6,%7}, {%8,%9}, {%0,%1,%2,%3};"
        : "+f"(c[0]), "+f"(c[1]), "+f"(c[2]), "+f"(c[3])
        : "r"(a[0]), "r"(a[1]), "r"(a[2]), "r"(a[3]), "r"(b[0]), "r"(b[1]));
}

// ---------------- K1: per-(n,c) spatial mean ----------------
__global__ void __launch_bounds__(256) mean_kernel(const float* __restrict__ x) {
    const int idx = blockIdx.x;  // n*256 + c
    const float4* p = reinterpret_cast<const float4*>(x + (size_t)idx * HW);
    float s = 0.f;
#pragma unroll
    for (int i = 0; i < 4; i++) {
        float4 v = p[threadIdx.x + i * 256];
        s += (v.x + v.y) + (v.z + v.w);
    }
#pragma unroll
    for (int o = 16; o; o >>= 1) s += __shfl_down_sync(0xffffffffu, s, o);
    __shared__ float ws[8];
    if ((threadIdx.x & 31) == 0) ws[threadIdx.x >> 5] = s;
    __syncthreads();
    if (threadIdx.x < 8) {
        float t = ws[threadIdx.x];
#pragma unroll
        for (int o = 4; o; o >>= 1) t += __shfl_down_sync(0xffu, t, o);
        if (threadIdx.x == 0) d_mean[idx] = t * (1.f / 4096.f);
    }
}

// ---------------- K2a: g = relu(conv_w@mean + b); build dynamic kernels ----------------
__global__ void __launch_bounds__(256) gker_kernel(
    const float* __restrict__ conv_w, const float* __restrict__ conv_b,
    const float* __restrict__ ckw, const float* __restrict__ ckb,
    const float* __restrict__ ck2w, const float* __restrict__ ck2b,
    const float* __restrict__ ckd4w, const float* __restrict__ ckd4b,
    const float* __restrict__ kw, const float* __restrict__ kb,
    const float* __restrict__ k2w, const float* __restrict__ k2b,
    const float* __restrict__ kd4w, const float* __restrict__ kd4b) {
    const int t = blockIdx.x * 256 + threadIdx.x;  // 0..2047 => (n, c)
    const int n = t >> 6, c = t & 63;
    const float* mrow = &d_mean[n * CIN];
    const float* wrow = &conv_w[c * CIN];
    float s = conv_b[c];
#pragma unroll 8
    for (int k = 0; k < CIN; k++) s = fmaf(mrow[k], wrow[k], s);
    const float g = fmaxf(s, 0.f);
    float* kp = &d_ker[(size_t)t * 43];
    float a = *ckw, b = *ckb;
#pragma unroll
    for (int i = 0; i < 25; i++) kp[i] = fmaf(a, fmaf(g, kw[i], kb[i]), b);
    a = *ck2w; b = *ck2b;
#pragma unroll
    for (int i = 0; i < 9; i++) kp[25 + i] = fmaf(a, fmaf(g, k2w[i], k2b[i]), b);
    a = *ckd4w; b = *ckd4b;
#pragma unroll
    for (int i = 0; i < 9; i++) kp[34 + i] = fmaf(a, fmaf(g, kd4w[i], kd4b[i]), b);
}

// ---------------- K2b: collapsed weights Wcat (tf32-rounded) and cbias ----------------
__global__ void __launch_bounds__(256) wcat_kernel(
    const float* __restrict__ fc_w, const float* __restrict__ fc_b,
    const float* __restrict__ fuse_w, const float* __restrict__ fuse_b) {
    const int m = blockIdx.x * 256 + threadIdx.x;
    if (m < MTOT * KCAT) {
        const int o = m / KCAT, cs = m % KCAT;
        const int b = cs >> 6, c = cs & 63;
        const float* fcr = &fc_w[o * 384 + b * 128];
        float s = 0.f;
#pragma unroll 4
        for (int j = 0; j < 128; j++) s = fmaf(fcr[j], fuse_w[j * 64 + c], s);
        d_Wcat[m] = f2tf32(s);
    } else {
        const int o = m - MTOT * KCAT;
        if (o < MTOT) {
            float s = fc_b[o];
            for (int j = 0; j < 384; j++)
                s = fmaf(fc_w[o * 384 + j], fuse_b[j & 127], s);
            d_cbias[o] = s;
        }
    }
}

// ---------------- unified tf32 mma GEMM: C[n][o][p] = act(A@B + bias) ----------------
// block BM x 128px, 8 warps (2 m-warps x 4 n-warps), warp tile (BM/2) x 32px,
// k-tile 16, double-buffered smem with register prefetch.
// MI = BM/32 m-fragments per warp. CVT: round A and B to tf32 at the smem store.
template <int BM, int KDIM, int MI, bool RELU, bool CVT>
__global__ void __launch_bounds__(256) mma_gemm_kernel(
    const float* __restrict__ A, const float* __restrict__ B,
    const float* __restrict__ bias, float* __restrict__ C, int Mtotal) {
    const int o0 = blockIdx.x * BM;
    const int p0 = blockIdx.y * 128;
    const int n = blockIdx.z;
    const float* Bn = B + (size_t)n * KDIM * HW;
    float* Cn = C + (size_t)n * Mtotal * HW;

    __shared__ __align__(16) float As[2][BM][20];   // [m][k] stride 20
    __shared__ __align__(16) float Bs[2][16][136];  // [k][p] stride 136

    const int tid = threadIdx.x;
    const int wid = tid >> 5, lane = tid & 31;
    const int wm = wid >> 2, wn = wid & 3;      // warp grid 2 x 4
    const int g = lane >> 2, tg = lane & 3;     // mma fragment coords

    // staging coordinates
    const int am = (BM == 64) ? (tid >> 2) : (tid >> 1);
    const int ak = (BM == 64) ? ((tid & 3) << 2) : ((tid & 1) << 3);
    const int kb = tid >> 4;
    const int pb = (tid & 15) << 3;

    float acc[MI][4][4];
#pragma unroll
    for (int i = 0; i < MI; i++)
#pragma unroll
        for (int j = 0; j < 4; j++)
#pragma unroll
            for (int q = 0; q < 4; q++) acc[i][j][q] = 0.f;

    constexpr int NKT = KDIM / 16;
    float4 ar0, ar1, br0, br1;

    // prologue: load + stage tile 0
    {
        const float* asrc = &A[(size_t)(o0 + am) * KDIM + ak];
        ar0 = *reinterpret_cast<const float4*>(asrc);
        if (BM == 128) ar1 = *reinterpret_cast<const float4*>(asrc + 4);
        const float* bsrc = &Bn[(size_t)kb * HW + p0 + pb];
        br0 = *reinterpret_cast<const float4*>(bsrc);
        br1 = *reinterpret_cast<const float4*>(bsrc + 4);
        if (CVT) { ar0 = cvt4(ar0); ar1 = cvt4(ar1); br0 = cvt4(br0); br1 = cvt4(br1); }
        *reinterpret_cast<float4*>(&As[0][am][ak]) = ar0;
        if (BM == 128) *reinterpret_cast<float4*>(&As[0][am][ak + 4]) = ar1;
        *reinterpret_cast<float4*>(&Bs[0][kb][pb]) = br0;
        *reinterpret_cast<float4*>(&Bs[0][kb][pb + 4]) = br1;
    }
    __syncthreads();

    for (int kt = 0; kt < NKT; kt++) {
        const int cur = kt & 1, nxt = cur ^ 1;
        // prefetch next tile into registers (hidden under compute)
        if (kt + 1 < NKT) {
            const int k0 = (kt + 1) * 16;
            const float* asrc = &A[(size_t)(o0 + am) * KDIM + k0 + ak];
            ar0 = *reinterpret_cast<const float4*>(asrc);
            if (BM == 128) ar1 = *reinterpret_cast<const float4*>(asrc + 4);
            const float* bsrc = &Bn[(size_t)(k0 + kb) * HW + p0 + pb];
            br0 = *reinterpret_cast<const float4*>(bsrc);
            br1 = *reinterpret_cast<const float4*>(bsrc + 4);
        }
        // compute on cur
#pragma unroll
        for (int ks = 0; ks < 16; ks += 8) {
            uint32_t af[MI][4], bf[4][2];
#pragma unroll
            for (int i = 0; i < MI; i++) {
                const int m = wm * (BM / 2) + i * 16 + g;
                af[i][0] = __float_as_uint(As[cur][m][ks + tg]);
                af[i][1] = __float_as_uint(As[cur][m + 8][ks + tg]);
                af[i][2] = __float_as_uint(As[cur][m][ks + tg + 4]);
                af[i][3] = __float_as_uint(As[cur][m + 8][ks + tg + 4]);
            }
#pragma unroll
            for (int j = 0; j < 4; j++) {
                const int col = wn * 32 + j * 8 + g;
                bf[j][0] = __float_as_uint(Bs[cur][ks + tg][col]);
                bf[j][1] = __float_as_uint(Bs[cur][ks + tg + 4][col]);
            }
#pragma unroll
            for (int i = 0; i < MI; i++)
#pragma unroll
                for (int j = 0; j < 4; j++) mma_tf32(acc[i][j], af[i], bf[j]);
        }
        // stage next tile
        if (kt + 1 < NKT) {
            if (CVT) { ar0 = cvt4(ar0); ar1 = cvt4(ar1); br0 = cvt4(br0); br1 = cvt4(br1); }
            *reinterpret_cast<float4*>(&As[nxt][am][ak]) = ar0;
            if (BM == 128) *reinterpret_cast<float4*>(&As[nxt][am][ak + 4]) = ar1;
            *reinterpret_cast<float4*>(&Bs[nxt][kb][pb]) = br0;
            *reinterpret_cast<float4*>(&Bs[nxt][kb][pb + 4]) = br1;
            __syncthreads();
        }
    }
    // epilogue
#pragma unroll
    for (int i = 0; i < MI; i++) {
        const int o = o0 + wm * (BM / 2) + i * 16 + g;
        const float bv0 = bias[o];
        const float bv1 = bias[o + 8];
#pragma unroll
        for (int j = 0; j < 4; j++) {
            const int px = p0 + wn * 32 + j * 8 + 2 * tg;
            float2 v0 = make_float2(acc[i][j][0] + bv0, acc[i][j][1] + bv0);
            float2 v1 = make_float2(acc[i][j][2] + bv1, acc[i][j][3] + bv1);
            if (RELU) {
                v0.x = fmaxf(v0.x, 0.f); v0.y = fmaxf(v0.y, 0.f);
                v1.x = fmaxf(v1.x, 0.f); v1.y = fmaxf(v1.y, 0.f);
            }
            *reinterpret_cast<float2*>(&Cn[(size_t)o * HW + px]) = v0;
            *reinterpret_cast<float2*>(&Cn[(size_t)(o + 8) * HW + px]) = v1;
        }
    }
}

// ---------------- K4a: three depthwise convs, smem 72x72 zero-padded tile ----------------
__global__ void __launch_bounds__(256) dw_kernel() {
    const int c = blockIdx.x;  // 64
    const int n = blockIdx.y;  // 32
    __shared__ float sm[72 * 72];
    __shared__ float kk[43];
    const int tid = threadIdx.x;
    for (int i = tid; i < 72 * 72; i += 256) sm[i] = 0.f;
    __syncthreads();
    const float* fb = d_f + ((size_t)n * CMC + c) * HW;
    for (int i = tid; i < HW; i += 256)
        sm[((i >> 6) + 4) * 72 + (i & 63) + 4] = fb[i];
    if (tid < 43) kk[tid] = d_ker[((size_t)n * CMC + c) * 43 + tid];
    __syncthreads();

    float* o1 = d_ocat + ((size_t)n * KCAT + c) * HW;
    float* o2 = o1 + (size_t)64 * HW;
    float* o3 = o1 + (size_t)128 * HW;

    for (int i = tid; i < HW; i += 256) {
        const int h = i >> 6, w = i & 63;
        float s1 = 0.f, s2 = 0.f, s3 = 0.f;
#pragma unroll
        for (int dy = 0; dy < 5; dy++)
#pragma unroll
            for (int dx = 0; dx < 5; dx++)
                s1 = fmaf(kk[dy * 5 + dx], sm[(h + dy + 2) * 72 + w + dx + 2], s1);
#pragma unroll
        for (int dy = 0; dy < 3; dy++)
#pragma unroll
            for (int dx = 0; dx < 3; dx++) {
                s2 = fmaf(kk[25 + dy * 3 + dx], sm[(h + 2 * dy + 2) * 72 + w + 2 * dx + 2], s2);
                s3 = fmaf(kk[34 + dy * 3 + dx], sm[(h + 4 * dy) * 72 + w + 4 * dx], s3);
            }
        // pre-round to tf32 so the mma GEMM needs no conversion
        o1[i] = f2tf32(s1);
        o2[i] = f2tf32(s2);
        o3[i] = f2tf32(s3);
    }
}

// ---------------- host launch ----------------
extern "C" void kernel_launch(void* const* d_in, const int* in_sizes, int n_in,
                              void* d_out, int out_size) {
    (void)in_sizes; (void)n_in; (void)out_size;
    const float* x      = (const float*)d_in[0];
    const float* conv_w = (const float*)d_in[1];
    const float* conv_b = (const float*)d_in[2];
    const float* ckw    = (const float*)d_in[3];
    const float* ckb    = (const float*)d_in[4];
    const float* ck2w   = (const float*)d_in[5];
    const float* ck2b   = (const float*)d_in[6];
    const float* ckd4w  = (const float*)d_in[7];
    const float* ckd4b  = (const float*)d_in[8];
    const float* kw     = (const float*)d_in[9];
    const float* kb     = (const float*)d_in[10];
    const float* k2w    = (const float*)d_in[11];
    const float* k2b    = (const float*)d_in[12];
    const float* kd4w   = (const float*)d_in[13];
    const float* kd4b   = (const float*)d_in[14];
    const float* fuse_w = (const float*)d_in[15];
    const float* fuse_b = (const float*)d_in[16];
    const float* fc_w   = (const float*)d_in[17];
    const float* fc_b   = (const float*)d_in[18];
    float* out = (float*)d_out;

    void *p_f = nullptr, *p_ocat = nullptr, *p_Wcat = nullptr, *p_cbias = nullptr;
    cudaGetSymbolAddress(&p_f, d_f);
    cudaGetSymbolAddress(&p_ocat, d_ocat);
    cudaGetSymbolAddress(&p_Wcat, d_Wcat);
    cudaGetSymbolAddress(&p_cbias, d_cbias);

    // K1: spatial means
    mean_kernel<<<NB * CIN, 256>>>(x);
    // K2a: g + dynamic depthwise kernels
    gker_kernel<<<8, 256>>>(conv_w, conv_b, ckw, ckb, ck2w, ck2b, ckd4w, ckd4b,
                            kw, kb, k2w, k2b, kd4w, kd4b);
    // K2b: collapsed fuse+fc weights (tf32-rounded)
    wcat_kernel<<<(MTOT * KCAT + MTOT + 255) / 256, 256>>>(fc_w, fc_b, fuse_w, fuse_b);
    // K3: f = relu(1x1 conv 256->64), tf32 tensor cores (cvt at smem store)
    mma_gemm_kernel<64, CIN, 2, true, true><<<dim3(1, HW / 128, NB), 256>>>(
        conv_w, x, conv_b, (float*)p_f, CMC);
    // K4a: dynamic depthwise (3 branches) -> ocat[n][192][p], tf32-rounded
    dw_kernel<<<dim3(CMC, NB), 256>>>();
    // K4b: out = Wcat @ ocat + cbias  (tf32 tensor cores, pre-rounded operands)
    mma_gemm_kernel<128, KCAT, 4, false, false><<<dim3(MTOT / 128, HW / 128, NB), 256>>>(
        (const float*)p_Wcat, (const float*)p_ocat, (const float*)p_cbias, out, MTOT);
}

// round 8
// speedup vs baseline: 1.8641x; 1.2105x over previous
#include <cuda_runtime.h>
#include <cstdint>
#include <cstddef>

#define HW   4096
#define NB   32
#define CIN  256
#define CMC  64
#define MTOT 384
#define KCAT 192

// ---------------- scratch (static device globals; no allocation) ----------------
__device__ float d_mean[NB * CIN];
__device__ float d_ker[NB * CMC * 43];
__device__ float d_Wcat[MTOT * KCAT];                    // tf32-rounded
__device__ float d_cbias[MTOT];
__device__ float d_f[(size_t)NB * CMC * HW];             // 33.5 MB
__device__ float d_ocat[(size_t)NB * KCAT * HW];         // 100.7 MB (tf32-rounded)

// ---------------- helpers ----------------
__device__ __forceinline__ float f2tf32(float f) {
    uint32_t r;
    asm("cvt.rna.tf32.f32 %0, %1;" : "=r"(r) : "f"(f));
    return __uint_as_float(r);
}
__device__ __forceinline__ void mma_tf32(float c[4], const uint32_t a[4],
                                         const uint32_t b[2]) {
    asm volatile(
        "mma.sync.aligned.m16n8k8.row.col.f32.tf32.tf32.f32 "
        "{%0,%1,%2,%3}, {%4,%5,%6,%7}, {%8,%9}, {%0,%1,%2,%3};"
        : "+f"(c[0]), "+f"(c[1]), "+f"(c[2]), "+f"(c[3])
        : "r"(a[0]), "r"(a[1]), "r"(a[2]), "r"(a[3]), "r"(b[0]), "r"(b[1]));
}
__device__ __forceinline__ void cp16(void* sptr, const void* g) {
    unsigned sa = (unsigned)__cvta_generic_to_shared(sptr);
    asm volatile("cp.async.cg.shared.global [%0], [%1], 16;" :: "r"(sa), "l"(g));
}
__device__ __forceinline__ void cp_commit() {
    asm volatile("cp.async.commit_group;" ::: "memory");
}

// ---------------- K1: per-(n,c) spatial mean ----------------
__global__ void __launch_bounds__(256) mean_kernel(const float* __restrict__ x) {
    const int idx = blockIdx.x;
    const float4* p = reinterpret_cast<const float4*>(x + (size_t)idx * HW);
    float s = 0.f;
#pragma unroll
    for (int i = 0; i < 4; i++) {
        float4 v = p[threadIdx.x + i * 256];
        s += (v.x + v.y) + (v.z + v.w);
    }
#pragma unroll
    for (int o = 16; o; o >>= 1) s += __shfl_down_sync(0xffffffffu, s, o);
    __shared__ float ws[8];
    if ((threadIdx.x & 31) == 0) ws[threadIdx.x >> 5] = s;
    __syncthreads();
    if (threadIdx.x < 8) {
        float t = ws[threadIdx.x];
#pragma unroll
        for (int o = 4; o; o >>= 1) t += __shfl_down_sync(0xffu, t, o);
        if (threadIdx.x == 0) d_mean[idx] = t * (1.f / 4096.f);
    }
}

// ---------------- K2a: g + dynamic kernels ----------------
__global__ void __launch_bounds__(256) gker_kernel(
    const float* __restrict__ conv_w, const float* __restrict__ conv_b,
    const float* __restrict__ ckw, const float* __restrict__ ckb,
    const float* __restrict__ ck2w, const float* __restrict__ ck2b,
    const float* __restrict__ ckd4w, const float* __restrict__ ckd4b,
    const float* __restrict__ kw, const float* __restrict__ kb,
    const float* __restrict__ k2w, const float* __restrict__ k2b,
    const float* __restrict__ kd4w, const float* __restrict__ kd4b) {
    const int t = blockIdx.x * 256 + threadIdx.x;
    const int n = t >> 6, c = t & 63;
    const float* mrow = &d_mean[n * CIN];
    const float* wrow = &conv_w[c * CIN];
    float s = conv_b[c];
#pragma unroll 8
    for (int k = 0; k < CIN; k++) s = fmaf(mrow[k], wrow[k], s);
    const float g = fmaxf(s, 0.f);
    float* kp = &d_ker[(size_t)t * 43];
    float a = *ckw, b = *ckb;
#pragma unroll
    for (int i = 0; i < 25; i++) kp[i] = fmaf(a, fmaf(g, kw[i], kb[i]), b);
    a = *ck2w; b = *ck2b;
#pragma unroll
    for (int i = 0; i < 9; i++) kp[25 + i] = fmaf(a, fmaf(g, k2w[i], k2b[i]), b);
    a = *ckd4w; b = *ckd4b;
#pragma unroll
    for (int i = 0; i < 9; i++) kp[34 + i] = fmaf(a, fmaf(g, kd4w[i], kd4b[i]), b);
}

// ---------------- K2b: collapsed weights Wcat (tf32-rounded) and cbias ----------------
__global__ void __launch_bounds__(256) wcat_kernel(
    const float* __restrict__ fc_w, const float* __restrict__ fc_b,
    const float* __restrict__ fuse_w, const float* __restrict__ fuse_b) {
    const int m = blockIdx.x * 256 + threadIdx.x;
    if (m < MTOT * KCAT) {
        const int o = m / KCAT, cs = m % KCAT;
        const int b = cs >> 6, c = cs & 63;
        const float* fcr = &fc_w[o * 384 + b * 128];
        float s = 0.f;
#pragma unroll 4
        for (int j = 0; j < 128; j++) s = fmaf(fcr[j], fuse_w[j * 64 + c], s);
        d_Wcat[m] = f2tf32(s);
    } else {
        const int o = m - MTOT * KCAT;
        if (o < MTOT) {
            float s = fc_b[o];
            for (int j = 0; j < 384; j++)
                s = fmaf(fc_w[o * 384 + j], fuse_b[j & 127], s);
            d_cbias[o] = s;
        }
    }
}

// ---------------- unified tf32 mma GEMM with 3-stage cp.async pipeline ----------------
// block BM x 128px, 8 warps (2m x 4n), warp tile (BM/2) x 32px, k-tile 16.
// CVT: round operands to tf32 at fragment load (ALU pipe is idle anyway).
template <int BM, int KDIM, int MI, bool RELU, bool CVT>
__global__ void __launch_bounds__(256) mma_gemm_kernel(
    const float* __restrict__ A, const float* __restrict__ B,
    const float* __restrict__ bias, float* __restrict__ C, int Mtotal) {
    constexpr int SA = BM * 20, SB = 16 * 136, SS = SA + SB;
    constexpr int NKT = KDIM / 16;
    extern __shared__ float smem[];

    const int o0 = blockIdx.x * BM;
    const int p0 = blockIdx.y * 128;
    const int n = blockIdx.z;
    const float* Bn = B + (size_t)n * KDIM * HW;
    float* Cn = C + (size_t)n * Mtotal * HW;

    const int tid = threadIdx.x;
    const int wid = tid >> 5, lane = tid & 31;
    const int wm = wid >> 2, wq = wid & 3;
    const int g = lane >> 2, tg = lane & 3;

    auto issue = [&](int s, int k0) {
        float* As_ = smem + s * SS;
        float* Bs_ = As_ + SA;
#pragma unroll
        for (int v = tid; v < BM * 4; v += 256) {
            const int row = v >> 2, kq = (v & 3) << 2;
            cp16(&As_[row * 20 + kq], &A[(size_t)(o0 + row) * KDIM + k0 + kq]);
        }
#pragma unroll
        for (int v = tid; v < 512; v += 256) {
            const int row = v >> 5, c4 = (v & 31) << 2;
            cp16(&Bs_[row * 136 + c4], &Bn[(size_t)(k0 + row) * HW + p0 + c4]);
        }
        cp_commit();
    };

    float acc[MI][4][4];
#pragma unroll
    for (int i = 0; i < MI; i++)
#pragma unroll
        for (int j = 0; j < 4; j++)
#pragma unroll
            for (int q = 0; q < 4; q++) acc[i][j][q] = 0.f;

    issue(0, 0);
    issue(1, 16);

    for (int kt = 0; kt < NKT; kt++) {
        if (kt == NKT - 1)
            asm volatile("cp.async.wait_group 0;" ::: "memory");
        else
            asm volatile("cp.async.wait_group 1;" ::: "memory");
        __syncthreads();
        if (kt + 2 < NKT) issue((kt + 2) % 3, (kt + 2) * 16);

        const float* As_ = smem + (kt % 3) * SS;
        const float* Bs_ = As_ + SA;
#pragma unroll
        for (int ks = 0; ks < 16; ks += 8) {
            uint32_t af[MI][4], bf[4][2];
#pragma unroll
            for (int i = 0; i < MI; i++) {
                const int m = wm * (BM / 2) + i * 16 + g;
                float a0 = As_[m * 20 + ks + tg];
                float a1 = As_[(m + 8) * 20 + ks + tg];
                float a2 = As_[m * 20 + ks + tg + 4];
                float a3 = As_[(m + 8) * 20 + ks + tg + 4];
                if (CVT) { a0 = f2tf32(a0); a1 = f2tf32(a1); a2 = f2tf32(a2); a3 = f2tf32(a3); }
                af[i][0] = __float_as_uint(a0);
                af[i][1] = __float_as_uint(a1);
                af[i][2] = __float_as_uint(a2);
                af[i][3] = __float_as_uint(a3);
            }
#pragma unroll
            for (int j = 0; j < 4; j++) {
                const int col = wq * 32 + j * 8 + g;
                float b0 = Bs_[(ks + tg) * 136 + col];
                float b1 = Bs_[(ks + tg + 4) * 136 + col];
                if (CVT) { b0 = f2tf32(b0); b1 = f2tf32(b1); }
                bf[j][0] = __float_as_uint(b0);
                bf[j][1] = __float_as_uint(b1);
            }
#pragma unroll
            for (int i = 0; i < MI; i++)
#pragma unroll
                for (int j = 0; j < 4; j++) mma_tf32(acc[i][j], af[i], bf[j]);
        }
    }
    // epilogue
#pragma unroll
    for (int i = 0; i < MI; i++) {
        const int o = o0 + wm * (BM / 2) + i * 16 + g;
        const float bv0 = bias[o];
        const float bv1 = bias[o + 8];
#pragma unroll
        for (int j = 0; j < 4; j++) {
            const int px = p0 + wq * 32 + j * 8 + 2 * tg;
            float2 v0 = make_float2(acc[i][j][0] + bv0, acc[i][j][1] + bv0);
            float2 v1 = make_float2(acc[i][j][2] + bv1, acc[i][j][3] + bv1);
            if (RELU) {
                v0.x = fmaxf(v0.x, 0.f); v0.y = fmaxf(v0.y, 0.f);
                v1.x = fmaxf(v1.x, 0.f); v1.y = fmaxf(v1.y, 0.f);
            }
            *reinterpret_cast<float2*>(&Cn[(size_t)o * HW + px]) = v0;
            *reinterpret_cast<float2*>(&Cn[(size_t)(o + 8) * HW + px]) = v1;
        }
    }
}

// ---------------- K4a: depthwise convs, 4 px/thread, float4 row loads ----------------
__global__ void __launch_bounds__(256) dw_kernel() {
    const int c = blockIdx.x;  // 64
    const int n = blockIdx.y;  // 32
    __shared__ float sm[72 * 72];
    __shared__ float kk[43];
    const int tid = threadIdx.x;
    for (int i = tid; i < 72 * 72; i += 256) sm[i] = 0.f;
    __syncthreads();
    const float* fb = d_f + ((size_t)n * CMC + c) * HW;
    for (int i = tid; i < HW; i += 256)
        sm[((i >> 6) + 4) * 72 + (i & 63) + 4] = fb[i];
    if (tid < 43) kk[tid] = d_ker[((size_t)n * CMC + c) * 43 + tid];
    __syncthreads();

    float* o1 = d_ocat + ((size_t)n * KCAT + c) * HW;
    float* o2 = o1 + (size_t)64 * HW;
    float* o3 = o1 + (size_t)128 * HW;

    const int w0 = (tid & 15) * 4;

#pragma unroll
    for (int pass = 0; pass < 4; pass++) {
        const int h = pass * 16 + (tid >> 4);
        float s1[4] = {0.f, 0.f, 0.f, 0.f};
        float s2[4] = {0.f, 0.f, 0.f, 0.f};
        float s3[4] = {0.f, 0.f, 0.f, 0.f};
        float rv[12];

        auto loadrow = [&](int ri) {
            const float4 a = *reinterpret_cast<const float4*>(&sm[ri * 72 + w0]);
            const float4 b = *reinterpret_cast<const float4*>(&sm[ri * 72 + w0 + 4]);
            const float4 d = *reinterpret_cast<const float4*>(&sm[ri * 72 + w0 + 8]);
            rv[0] = a.x; rv[1] = a.y; rv[2] = a.z; rv[3] = a.w;
            rv[4] = b.x; rv[5] = b.y; rv[6] = b.z; rv[7] = b.w;
            rv[8] = d.x; rv[9] = d.y; rv[10] = d.z; rv[11] = d.w;
        };
        auto b1row = [&](int dy) {
#pragma unroll
            for (int dx = 0; dx < 5; dx++) {
                const float kv = kk[dy * 5 + dx];
#pragma unroll
                for (int px = 0; px < 4; px++) s1[px] = fmaf(kv, rv[px + dx + 2], s1[px]);
            }
        };
        auto b2row = [&](int dy2) {
#pragma unroll
            for (int dx = 0; dx < 3; dx++) {
                const float kv = kk[25 + dy2 * 3 + dx];
#pragma unroll
                for (int px = 0; px < 4; px++) s2[px] = fmaf(kv, rv[px + 2 * dx + 2], s2[px]);
            }
        };
        auto b3row = [&](int dy4) {
#pragma unroll
            for (int dx = 0; dx < 3; dx++) {
                const float kv = kk[34 + dy4 * 3 + dx];
#pragma unroll
                for (int px = 0; px < 4; px++) s3[px] = fmaf(kv, rv[px + 4 * dx], s3[px]);
            }
        };

        loadrow(h);     b3row(0);
        loadrow(h + 2); b1row(0); b2row(0);
        loadrow(h + 3); b1row(1);
        loadrow(h + 4); b1row(2); b2row(1); b3row(1);
        loadrow(h + 5); b1row(3);
        loadrow(h + 6); b1row(4); b2row(2);
        loadrow(h + 8); b3row(2);

        const int i = h * 64 + w0;
        float4 v;
        v.x = f2tf32(s1[0]); v.y = f2tf32(s1[1]); v.z = f2tf32(s1[2]); v.w = f2tf32(s1[3]);
        *reinterpret_cast<float4*>(&o1[i]) = v;
        v.x = f2tf32(s2[0]); v.y = f2tf32(s2[1]); v.z = f2tf32(s2[2]); v.w = f2tf32(s2[3]);
        *reinterpret_cast<float4*>(&o2[i]) = v;
        v.x = f2tf32(s3[0]); v.y = f2tf32(s3[1]); v.z = f2tf32(s3[2]); v.w = f2tf32(s3[3]);
        *reinterpret_cast<float4*>(&o3[i]) = v;
    }
}

// ---------------- host launch ----------------
extern "C" void kernel_launch(void* const* d_in, const int* in_sizes, int n_in,
                              void* d_out, int out_size) {
    (void)in_sizes; (void)n_in; (void)out_size;
    const float* x      = (const float*)d_in[0];
    const float* conv_w = (const float*)d_in[1];
    const float* conv_b = (const float*)d_in[2];
    const float* ckw    = (const float*)d_in[3];
    const float* ckb    = (const float*)d_in[4];
    const float* ck2w   = (const float*)d_in[5];
    const float* ck2b   = (const float*)d_in[6];
    const float* ckd4w  = (const float*)d_in[7];
    const float* ckd4b  = (const float*)d_in[8];
    const float* kw     = (const float*)d_in[9];
    const float* kb     = (const float*)d_in[10];
    const float* k2w    = (const float*)d_in[11];
    const float* k2b    = (const float*)d_in[12];
    const float* kd4w   = (const float*)d_in[13];
    const float* kd4b   = (const float*)d_in[14];
    const float* fuse_w = (const float*)d_in[15];
    const float* fuse_b = (const float*)d_in[16];
    const float* fc_w   = (const float*)d_in[17];
    const float* fc_b   = (const float*)d_in[18];
    float* out = (float*)d_out;

    void *p_f = nullptr, *p_ocat = nullptr, *p_Wcat = nullptr, *p_cbias = nullptr;
    cudaGetSymbolAddress(&p_f, d_f);
    cudaGetSymbolAddress(&p_ocat, d_ocat);
    cudaGetSymbolAddress(&p_Wcat, d_Wcat);
    cudaGetSymbolAddress(&p_cbias, d_cbias);

    constexpr int SMEM_K3  = 3 * (64 * 20 + 16 * 136) * 4;   // 41472 B
    constexpr int SMEM_K4B = 3 * (128 * 20 + 16 * 136) * 4;  // 56832 B
    cudaFuncSetAttribute(mma_gemm_kernel<64, CIN, 2, true, true>,
                         cudaFuncAttributeMaxDynamicSharedMemorySize, SMEM_K3);
    cudaFuncSetAttribute(mma_gemm_kernel<128, KCAT, 4, false, false>,
                         cudaFuncAttributeMaxDynamicSharedMemorySize, SMEM_K4B);

    // K1: spatial means
    mean_kernel<<<NB * CIN, 256>>>(x);
    // K2a: g + dynamic depthwise kernels
    gker_kernel<<<8, 256>>>(conv_w, conv_b, ckw, ckb, ck2w, ck2b, ckd4w, ckd4b,
                            kw, kb, k2w, k2b, kd4w, kd4b);
    // K2b: collapsed fuse+fc weights (tf32-rounded)
    wcat_kernel<<<(MTOT * KCAT + MTOT + 255) / 256, 256>>>(fc_w, fc_b, fuse_w, fuse_b);
    // K3: f = relu(1x1 conv 256->64), tf32 mma, cp.async pipeline, cvt at fragment load
    mma_gemm_kernel<64, CIN, 2, true, true>
        <<<dim3(1, HW / 128, NB), 256, SMEM_K3>>>(conv_w, x, conv_b, (float*)p_f, CMC);
    // K4a: dynamic depthwise (3 branches) -> ocat, tf32-rounded
    dw_kernel<<<dim3(CMC, NB), 256>>>();
    // K4b: out = Wcat @ ocat + cbias (tf32 mma, pre-rounded operands)
    mma_gemm_kernel<128, KCAT, 4, false, false>
        <<<dim3(MTOT / 128, HW / 128, NB), 256, SMEM_K4B>>>(
            (const float*)p_Wcat, (const float*)p_ocat, (const float*)p_cbias, out, MTOT);
}